// round 5
// baseline (speedup 1.0000x reference)
#include <cuda_runtime.h>
#include <math.h>

// AdaFace logit adjustment, two-phase:
//  1) stats_kernel (1 block, ~2us): norm stats + per-row (g_ang, g_add, target
//     flat index) into __device__ globals. No access to the 400MB matrix.
//  2) stream_kernel (1184 blocks, exactly one wave at 8 blocks/SM): contiguous
//     per-block chunks, 4x-unrolled float4 stream out = in*64, with the <=2
//     in-chunk target elements patched in-register (acos/cos margin) before
//     scaling. No scattered gather anywhere.

#define B_ROWS   1024
#define SCALE    64.0f
#define MARGIN   0.4f
#define H_CONST  0.333f
#define EPS_CONST 1e-3f
#define THREADS  256
#define NBLOCKS  (148 * 8)
#define MAXT     4

__device__ float d_ga[B_ROWS];   // per-row angular margin
__device__ float d_gd[B_ROWS];   // per-row additive margin
__device__ int   d_tgt[B_ROWS];  // per-row target flat element index

// ---------------------------------------------------------------------------
// Phase 1: stats + per-row margin params. 1 block, 1024 threads. ~4KB traffic.
// ---------------------------------------------------------------------------
__global__ void __launch_bounds__(B_ROWS)
stats_kernel(const float* __restrict__ norms,
             const int*   __restrict__ labels,
             int C) {
    __shared__ float red[32];
    const int tid = threadIdx.x;

    float x = norms[tid];
    x = fminf(fmaxf(x, 1e-3f), 100.0f);

    // block sum -> mean
    float v = x;
    #pragma unroll
    for (int o = 16; o > 0; o >>= 1) v += __shfl_down_sync(0xffffffffu, v, o);
    int lane = tid & 31, warp = tid >> 5;
    if (lane == 0) red[warp] = v;
    __syncthreads();
    if (warp == 0) {
        v = red[lane];
        #pragma unroll
        for (int o = 16; o > 0; o >>= 1) v += __shfl_down_sync(0xffffffffu, v, o);
        if (lane == 0) red[0] = v;
    }
    __syncthreads();
    float mean = red[0] * (1.0f / B_ROWS);
    __syncthreads();

    // block sum of squared deviations -> unbiased std (ddof=1)
    float dv = x - mean;
    v = dv * dv;
    #pragma unroll
    for (int o = 16; o > 0; o >>= 1) v += __shfl_down_sync(0xffffffffu, v, o);
    if (lane == 0) red[warp] = v;
    __syncthreads();
    if (warp == 0) {
        v = red[lane];
        #pragma unroll
        for (int o = 16; o > 0; o >>= 1) v += __shfl_down_sync(0xffffffffu, v, o);
        if (lane == 0) red[0] = v;
    }
    __syncthreads();
    float stdv = sqrtf(red[0] * (1.0f / (B_ROWS - 1)));

    float ms = (x - mean) * (H_CONST / (stdv + EPS_CONST));
    ms = fminf(fmaxf(ms, -1.0f), 1.0f);

    d_ga[tid]  = -MARGIN * ms;
    d_gd[tid]  = MARGIN + MARGIN * ms;
    d_tgt[tid] = tid * C + labels[tid];   // < 102.4M, fits int
}

// ---------------------------------------------------------------------------
// Phase 2: streaming scale + inline patch. Low-reg, exactly one wave.
// ---------------------------------------------------------------------------
__global__ void __launch_bounds__(THREADS, 8)
stream_kernel(const float4* __restrict__ in,
              float4* __restrict__ out,
              int C, int n4) {
    __shared__ int   s_ntgt;
    __shared__ int   s_tgt_i4[MAXT];
    __shared__ int   s_tgt_c[MAXT];
    __shared__ float s_ga[MAXT];
    __shared__ float s_gd[MAXT];

    const int tid = threadIdx.x;

    int chunk4 = (n4 + gridDim.x - 1) / gridDim.x;
    int i40 = blockIdx.x * chunk4;
    if (i40 >= n4) return;
    int i41 = min(n4, i40 + chunk4);

    // targets inside this chunk (chunk spans <= 2 rows: chunk < C)
    if (tid == 0) s_ntgt = 0;
    __syncthreads();
    {
        int e0 = i40 * 4;
        int e1 = i41 * 4;                 // exclusive
        int r0 = e0 / C;
        int r1 = (e1 - 1) / C;
        int nrows = r1 - r0 + 1;          // 1 or 2
        if (tid < nrows && tid < MAXT) {
            int r = r0 + tid;
            int tgt = d_tgt[r];
            if (tgt >= e0 && tgt < e1) {
                int slot = atomicAdd(&s_ntgt, 1);
                s_tgt_i4[slot] = tgt >> 2;
                s_tgt_c[slot]  = tgt & 3;
                s_ga[slot]     = d_ga[r];
                s_gd[slot]     = d_gd[r];
            }
        }
    }
    __syncthreads();
    const int ntgt = s_ntgt;

    auto patch = [&](float4& v, int i4) {
        for (int t = 0; t < ntgt; t++) {
            if (i4 == s_tgt_i4[t]) {
                int c = s_tgt_c[t];
                float tv = (c == 0) ? v.x : (c == 1) ? v.y : (c == 2) ? v.z : v.w;
                float theta = acosf(tv) + s_ga[t];
                theta = fminf(fmaxf(theta, EPS_CONST), (float)M_PI - EPS_CONST);
                float nt = cosf(theta) - s_gd[t];
                switch (c) {
                    case 0: v.x = nt; break;
                    case 1: v.y = nt; break;
                    case 2: v.z = nt; break;
                    default: v.w = nt; break;
                }
            }
        }
    };

    int i = i40 + tid;
    for (; i + 3 * THREADS < i41; i += 4 * THREADS) {
        float4 v0 = __ldcs(&in[i]);
        float4 v1 = __ldcs(&in[i + THREADS]);
        float4 v2 = __ldcs(&in[i + 2 * THREADS]);
        float4 v3 = __ldcs(&in[i + 3 * THREADS]);
        if (ntgt) {
            patch(v0, i);
            patch(v1, i + THREADS);
            patch(v2, i + 2 * THREADS);
            patch(v3, i + 3 * THREADS);
        }
        v0.x *= SCALE; v0.y *= SCALE; v0.z *= SCALE; v0.w *= SCALE;
        v1.x *= SCALE; v1.y *= SCALE; v1.z *= SCALE; v1.w *= SCALE;
        v2.x *= SCALE; v2.y *= SCALE; v2.z *= SCALE; v2.w *= SCALE;
        v3.x *= SCALE; v3.y *= SCALE; v3.z *= SCALE; v3.w *= SCALE;
        __stcs(&out[i],               v0);
        __stcs(&out[i + THREADS],     v1);
        __stcs(&out[i + 2 * THREADS], v2);
        __stcs(&out[i + 3 * THREADS], v3);
    }
    for (; i < i41; i += THREADS) {
        float4 v = __ldcs(&in[i]);
        if (ntgt) patch(v, i);
        v.x *= SCALE; v.y *= SCALE; v.z *= SCALE; v.w *= SCALE;
        __stcs(&out[i], v);
    }
}

// ---------------------------------------------------------------------------
extern "C" void kernel_launch(void* const* d_in, const int* in_sizes, int n_in,
                              void* d_out, int out_size) {
    const float* logits = (const float*)d_in[0];
    const float* norms  = (const float*)d_in[1];
    const int*   labels = (const int*)d_in[2];
    float* out = (float*)d_out;

    int total = out_size;            // B*C = 102,400,000
    int C = total / B_ROWS;          // 100000
    int n4 = total / 4;              // 25,600,000 (C % 4 == 0)

    stats_kernel<<<1, B_ROWS>>>(norms, labels, C);
    stream_kernel<<<NBLOCKS, THREADS>>>((const float4*)logits, (float4*)out, C, n4);
}

// round 11
// speedup vs baseline: 1.0819x; 1.0819x over previous
#include <cuda_runtime.h>
#include <math.h>

// AdaFace logit adjustment, fused single streaming kernel (R4 structure),
// launched as EXACTLY ONE WAVE: 148 SMs x 6 blocks/SM = 888 blocks at
// __launch_bounds__(256, 6) (reg cap 42 > the 40 this kernel needs, so the
// 4-deep float4 load batch keeps its MLP — the R5 regression came from a
// 32-reg cap serializing the loads).
//
//   out = logits * 64, except out[r, labels[r]] =
//         (cos(clip(acos(t)+g_ang, eps, pi-eps)) - g_add) * 64
// B=1024, C=100000, fp32. 800 MB HBM round trip.

#define B_ROWS   1024
#define SCALE    64.0f
#define MARGIN   0.4f
#define H_CONST  0.333f
#define EPS_CONST 1e-3f
#define THREADS  256
#define NBLOCKS  (148 * 6)
#define MAXT     4

__device__ __forceinline__ float block_sum_256(float v, float* red) {
    #pragma unroll
    for (int o = 16; o > 0; o >>= 1)
        v += __shfl_down_sync(0xffffffffu, v, o);
    int lane = threadIdx.x & 31;
    int warp = threadIdx.x >> 5;
    if (lane == 0) red[warp] = v;
    __syncthreads();
    if (warp == 0) {
        v = (lane < THREADS / 32) ? red[lane] : 0.0f;
        #pragma unroll
        for (int o = 4; o > 0; o >>= 1)
            v += __shfl_down_sync(0xffffffffu, v, o);
        if (lane == 0) red[0] = v;
    }
    __syncthreads();
    float r = red[0];
    __syncthreads();
    return r;
}

__global__ void __launch_bounds__(THREADS, 6)
fused_kernel(const float4* __restrict__ in,
             float4* __restrict__ out,
             const float* __restrict__ norms,
             const int*   __restrict__ labels,
             int C, int n4) {
    __shared__ float red[THREADS / 32];
    __shared__ int   s_ntgt;
    __shared__ int   s_tgt_i4[MAXT];
    __shared__ int   s_tgt_c[MAXT];
    __shared__ float s_ga[MAXT];
    __shared__ float s_gd[MAXT];

    const int tid = threadIdx.x;

    // ---- block-contiguous chunk ----
    int chunk4 = (n4 + gridDim.x - 1) / gridDim.x;
    int i40 = blockIdx.x * chunk4;
    if (i40 >= n4) return;
    int i41 = min(n4, i40 + chunk4);

    // ---- norm stats (redundant per block; 4KB broadcast from L2) ----
    float xl[B_ROWS / THREADS];
    float acc = 0.0f;
    #pragma unroll
    for (int k = 0; k < B_ROWS / THREADS; k++) {
        float x = norms[tid + k * THREADS];
        x = fminf(fmaxf(x, 1e-3f), 100.0f);
        xl[k] = x;
        acc += x;
    }
    float mean = block_sum_256(acc, red) * (1.0f / B_ROWS);
    float vacc = 0.0f;
    #pragma unroll
    for (int k = 0; k < B_ROWS / THREADS; k++) {
        float d = xl[k] - mean;
        vacc += d * d;
    }
    float stdv = sqrtf(block_sum_256(vacc, red) * (1.0f / (B_ROWS - 1)));
    float inv_sh = H_CONST / (stdv + EPS_CONST);

    // ---- find targets inside this chunk (chunk ~461KB spans <= 3 rows) ----
    if (tid == 0) s_ntgt = 0;
    __syncthreads();
    {
        int e0 = i40 * 4;
        int e1 = i41 * 4;                 // exclusive; fits int (<= 102.4M)
        int r0 = e0 / C;
        int r1 = (e1 - 1) / C;
        int nrows = r1 - r0 + 1;          // 1..3
        if (tid < nrows && tid < MAXT) {
            int r = r0 + tid;
            int lbl = labels[r];
            int tgt = r * C + lbl;        // < 102.4M, fits int
            if (tgt >= e0 && tgt < e1) {
                float x = fminf(fmaxf(norms[r], 1e-3f), 100.0f);
                float ms = (x - mean) * inv_sh;
                ms = fminf(fmaxf(ms, -1.0f), 1.0f);
                int slot = atomicAdd(&s_ntgt, 1);
                s_tgt_i4[slot] = tgt >> 2;
                s_tgt_c[slot]  = tgt & 3;
                s_ga[slot]     = -MARGIN * ms;
                s_gd[slot]     = MARGIN + MARGIN * ms;
            }
        }
    }
    __syncthreads();
    const int ntgt = s_ntgt;

    // ---- stream the chunk ----
    auto patch = [&](float4& v, int i4) {
        for (int t = 0; t < ntgt; t++) {
            if (i4 == s_tgt_i4[t]) {
                int c = s_tgt_c[t];
                float tv = (c == 0) ? v.x : (c == 1) ? v.y : (c == 2) ? v.z : v.w;
                float theta = acosf(tv) + s_ga[t];
                theta = fminf(fmaxf(theta, EPS_CONST), (float)M_PI - EPS_CONST);
                float nt = cosf(theta) - s_gd[t];
                switch (c) {
                    case 0: v.x = nt; break;
                    case 1: v.y = nt; break;
                    case 2: v.z = nt; break;
                    default: v.w = nt; break;
                }
            }
        }
    };

    int i = i40 + tid;
    for (; i + 3 * THREADS < i41; i += 4 * THREADS) {
        float4 v0 = __ldcs(&in[i]);
        float4 v1 = __ldcs(&in[i + THREADS]);
        float4 v2 = __ldcs(&in[i + 2 * THREADS]);
        float4 v3 = __ldcs(&in[i + 3 * THREADS]);
        if (ntgt) {
            patch(v0, i);
            patch(v1, i + THREADS);
            patch(v2, i + 2 * THREADS);
            patch(v3, i + 3 * THREADS);
        }
        v0.x *= SCALE; v0.y *= SCALE; v0.z *= SCALE; v0.w *= SCALE;
        v1.x *= SCALE; v1.y *= SCALE; v1.z *= SCALE; v1.w *= SCALE;
        v2.x *= SCALE; v2.y *= SCALE; v2.z *= SCALE; v2.w *= SCALE;
        v3.x *= SCALE; v3.y *= SCALE; v3.z *= SCALE; v3.w *= SCALE;
        __stcs(&out[i],               v0);
        __stcs(&out[i + THREADS],     v1);
        __stcs(&out[i + 2 * THREADS], v2);
        __stcs(&out[i + 3 * THREADS], v3);
    }
    for (; i < i41; i += THREADS) {
        float4 v = __ldcs(&in[i]);
        if (ntgt) patch(v, i);
        v.x *= SCALE; v.y *= SCALE; v.z *= SCALE; v.w *= SCALE;
        __stcs(&out[i], v);
    }
}

extern "C" void kernel_launch(void* const* d_in, const int* in_sizes, int n_in,
                              void* d_out, int out_size) {
    const float* logits = (const float*)d_in[0];
    const float* norms  = (const float*)d_in[1];
    const int*   labels = (const int*)d_in[2];
    float* out = (float*)d_out;

    int total = out_size;            // B*C = 102,400,000
    int C = total / B_ROWS;          // 100000
    int n4 = total / 4;              // 25,600,000 (C % 4 == 0)

    fused_kernel<<<NBLOCKS, THREADS>>>((const float4*)logits, (float4*)out,
                                       norms, labels, C, n4);
}

// round 12
// speedup vs baseline: 1.2186x; 1.1264x over previous
#include <cuda_runtime.h>
#include <math.h>

// AdaFace logit adjustment, fused single streaming kernel.
//   out = logits * 64, except out[r, labels[r]] =
//         (cos(clip(acos(t)+g_ang, eps, pi-eps)) - g_add) * 64
// B=1024, C=100000, fp32. 800 MB HBM round trip.
//
// Scheduling: 3552 blocks (24 launched/SM, 6 resident at regs=40) => 4 waves.
// The HW CTA scheduler backfills as blocks finish, so per-CTA finish-time
// spread is absorbed by later-wave blocks (R11 showed exactly-one-wave static
// chunking LOSES to multi-wave: DRAM 70.9% vs 74.1%). Chunk ~115KB, spans
// <=2 rows. Natural codegen (no min-blocks cap) preserves the 4-deep float4
// load batch (MLP) that the R5 32-reg cap destroyed.

#define B_ROWS   1024
#define SCALE    64.0f
#define MARGIN   0.4f
#define H_CONST  0.333f
#define EPS_CONST 1e-3f
#define THREADS  256
#define NBLOCKS  (148 * 24)
#define MAXT     4

__device__ __forceinline__ float block_sum_256(float v, float* red) {
    #pragma unroll
    for (int o = 16; o > 0; o >>= 1)
        v += __shfl_down_sync(0xffffffffu, v, o);
    int lane = threadIdx.x & 31;
    int warp = threadIdx.x >> 5;
    if (lane == 0) red[warp] = v;
    __syncthreads();
    if (warp == 0) {
        v = (lane < THREADS / 32) ? red[lane] : 0.0f;
        #pragma unroll
        for (int o = 4; o > 0; o >>= 1)
            v += __shfl_down_sync(0xffffffffu, v, o);
        if (lane == 0) red[0] = v;
    }
    __syncthreads();
    float r = red[0];
    __syncthreads();
    return r;
}

__global__ void __launch_bounds__(THREADS)
fused_kernel(const float4* __restrict__ in,
             float4* __restrict__ out,
             const float* __restrict__ norms,
             const int*   __restrict__ labels,
             int C, int n4) {
    __shared__ float red[THREADS / 32];
    __shared__ int   s_ntgt;
    __shared__ int   s_tgt_i4[MAXT];
    __shared__ int   s_tgt_c[MAXT];
    __shared__ float s_ga[MAXT];
    __shared__ float s_gd[MAXT];

    const int tid = threadIdx.x;

    // ---- block-contiguous chunk ----
    int chunk4 = (n4 + gridDim.x - 1) / gridDim.x;
    int i40 = blockIdx.x * chunk4;
    if (i40 >= n4) return;
    int i41 = min(n4, i40 + chunk4);

    // ---- norm stats (redundant per block; 4KB broadcast from L2) ----
    float xl[B_ROWS / THREADS];
    float acc = 0.0f;
    #pragma unroll
    for (int k = 0; k < B_ROWS / THREADS; k++) {
        float x = norms[tid + k * THREADS];
        x = fminf(fmaxf(x, 1e-3f), 100.0f);
        xl[k] = x;
        acc += x;
    }
    float mean = block_sum_256(acc, red) * (1.0f / B_ROWS);
    float vacc = 0.0f;
    #pragma unroll
    for (int k = 0; k < B_ROWS / THREADS; k++) {
        float d = xl[k] - mean;
        vacc += d * d;
    }
    float stdv = sqrtf(block_sum_256(vacc, red) * (1.0f / (B_ROWS - 1)));
    float inv_sh = H_CONST / (stdv + EPS_CONST);

    // ---- find targets inside this chunk (~115KB chunk spans <= 2 rows) ----
    if (tid == 0) s_ntgt = 0;
    __syncthreads();
    {
        int e0 = i40 * 4;
        int e1 = i41 * 4;                 // exclusive; fits int (<= 102.4M)
        int r0 = e0 / C;
        int r1 = (e1 - 1) / C;
        int nrows = r1 - r0 + 1;          // 1..2
        if (tid < nrows && tid < MAXT) {
            int r = r0 + tid;
            int lbl = labels[r];
            int tgt = r * C + lbl;        // < 102.4M, fits int
            if (tgt >= e0 && tgt < e1) {
                float x = fminf(fmaxf(norms[r], 1e-3f), 100.0f);
                float ms = (x - mean) * inv_sh;
                ms = fminf(fmaxf(ms, -1.0f), 1.0f);
                int slot = atomicAdd(&s_ntgt, 1);
                s_tgt_i4[slot] = tgt >> 2;
                s_tgt_c[slot]  = tgt & 3;
                s_ga[slot]     = -MARGIN * ms;
                s_gd[slot]     = MARGIN + MARGIN * ms;
            }
        }
    }
    __syncthreads();
    const int ntgt = s_ntgt;

    // ---- stream the chunk ----
    auto patch = [&](float4& v, int i4) {
        for (int t = 0; t < ntgt; t++) {
            if (i4 == s_tgt_i4[t]) {
                int c = s_tgt_c[t];
                float tv = (c == 0) ? v.x : (c == 1) ? v.y : (c == 2) ? v.z : v.w;
                float theta = acosf(tv) + s_ga[t];
                theta = fminf(fmaxf(theta, EPS_CONST), (float)M_PI - EPS_CONST);
                float nt = cosf(theta) - s_gd[t];
                switch (c) {
                    case 0: v.x = nt; break;
                    case 1: v.y = nt; break;
                    case 2: v.z = nt; break;
                    default: v.w = nt; break;
                }
            }
        }
    };

    int i = i40 + tid;
    for (; i + 3 * THREADS < i41; i += 4 * THREADS) {
        float4 v0 = __ldcs(&in[i]);
        float4 v1 = __ldcs(&in[i + THREADS]);
        float4 v2 = __ldcs(&in[i + 2 * THREADS]);
        float4 v3 = __ldcs(&in[i + 3 * THREADS]);
        if (ntgt) {
            patch(v0, i);
            patch(v1, i + THREADS);
            patch(v2, i + 2 * THREADS);
            patch(v3, i + 3 * THREADS);
        }
        v0.x *= SCALE; v0.y *= SCALE; v0.z *= SCALE; v0.w *= SCALE;
        v1.x *= SCALE; v1.y *= SCALE; v1.z *= SCALE; v1.w *= SCALE;
        v2.x *= SCALE; v2.y *= SCALE; v2.z *= SCALE; v2.w *= SCALE;
        v3.x *= SCALE; v3.y *= SCALE; v3.z *= SCALE; v3.w *= SCALE;
        __stcs(&out[i],               v0);
        __stcs(&out[i + THREADS],     v1);
        __stcs(&out[i + 2 * THREADS], v2);
        __stcs(&out[i + 3 * THREADS], v3);
    }
    for (; i < i41; i += THREADS) {
        float4 v = __ldcs(&in[i]);
        if (ntgt) patch(v, i);
        v.x *= SCALE; v.y *= SCALE; v.z *= SCALE; v.w *= SCALE;
        __stcs(&out[i], v);
    }
}

extern "C" void kernel_launch(void* const* d_in, const int* in_sizes, int n_in,
                              void* d_out, int out_size) {
    const float* logits = (const float*)d_in[0];
    const float* norms  = (const float*)d_in[1];
    const int*   labels = (const int*)d_in[2];
    float* out = (float*)d_out;

    int total = out_size;            // B*C = 102,400,000
    int C = total / B_ROWS;          // 100000
    int n4 = total / 4;              // 25,600,000 (C % 4 == 0)

    fused_kernel<<<NBLOCKS, THREADS>>>((const float4*)logits, (float4*)out,
                                       norms, labels, C, n4);
}